// round 15
// baseline (speedup 1.0000x reference)
#include <cuda_runtime.h>
#include <cuda_fp16.h>
#include <math.h>
#include <stdint.h>

#define BB 8
#define CIN 128
#define COUT 128
#define HH 64
#define WW 64
#define KHW 3
#define KK 9
#define PP 4096            // Ho*Wo
#define MK 1152            // Cin*K  (reduction dim, reordered as m' = k*128 + c)
#define WPAIR 576          // MK/2
#define NKT 36             // MK/32 k-tiles

// Channel-last input: g_inpt[b][hw][c]  (16.8 MB)
__device__ float g_inpt[(size_t)BB * PP * CIN];
// Packed cols: half2(channel c, c+1) at row w = k*64 + c/2.  75.5 MB
__device__ uint32_t g_colsp[(size_t)BB * WPAIR * PP];
// Pre-tiled weights: [ktile][co][16 words], word j = half2(m'=kt*32+2j, +1)
__device__ uint32_t g_wtp[(size_t)NKT * COUT * 16];

// ---------------------------------------------------------------------------
// Input transpose: [b][c][hw] -> [b][hw][c], 32x32 smem tiles.
// ---------------------------------------------------------------------------
__global__ __launch_bounds__(256) void transpose_kernel(const float* __restrict__ input)
{
    __shared__ float tile[32][33];
    int b   = blockIdx.z;
    int hw0 = blockIdx.x * 32;
    int c0  = blockIdx.y * 32;
    int tx = threadIdx.x & 31;
    int ty = threadIdx.x >> 5;      // 0..7
    #pragma unroll
    for (int j = 0; j < 4; j++) {
        int c = c0 + ty + 8 * j;
        tile[ty + 8 * j][tx] = input[((size_t)b * CIN + c) * PP + hw0 + tx];
    }
    __syncthreads();
    #pragma unroll
    for (int j = 0; j < 4; j++) {
        int hw = hw0 + ty + 8 * j;
        g_inpt[((size_t)b * PP + hw) * CIN + c0 + tx] = tile[tx][ty + 8 * j];
    }
}

// ---------------------------------------------------------------------------
// Weight prep: reorder to m' = k*128 + c, convert to half2 pairs, tile for
// the GEMM's cp.async A loads.
// ---------------------------------------------------------------------------
__global__ __launch_bounds__(256) void wprep_kernel(const float* __restrict__ Wt)
{
    int idx = blockIdx.x * blockDim.x + threadIdx.x;
    if (idx >= NKT * COUT * 16) return;
    int kt = idx >> 11;
    int co = (idx >> 4) & 127;
    int j  = idx & 15;
    int m0 = kt * 32 + 2 * j;
    int k  = m0 >> 7;
    int c  = m0 & 127;
    float w0 = Wt[(size_t)co * MK + c * KK + k];
    float w1 = Wt[(size_t)co * MK + (c + 1) * KK + k];
    __half2 h = __halves2half2(__float2half_rn(w0), __float2half_rn(w1));
    g_wtp[idx] = *reinterpret_cast<uint32_t*>(&h);
}

// ---------------------------------------------------------------------------
// Deformable im2col from channel-last input -> packed half2 cols.
// Thread owns (b, k, p): 4 corner rows of 128 contiguous channels each,
// gathered with float4 loads (128 LDG.128 instead of 512 LDG.32).
// ---------------------------------------------------------------------------
__global__ __launch_bounds__(256) void im2col_kernel(
    const float* __restrict__ offset,
    const float* __restrict__ mask)
{
    int gid = blockIdx.x * blockDim.x + threadIdx.x;
    if (gid >= BB * KK * PP) return;
    int p = gid & (PP - 1);
    int t = gid >> 12;
    int k = t % KK;
    int b = t / KK;
    int y = p >> 6;
    int x = p & 63;

    float offy = offset[((size_t)b * 2 * KK + 2 * k) * PP + p];
    float offx = offset[((size_t)b * 2 * KK + 2 * k + 1) * PP + p];
    float mval = mask[((size_t)b * KK + k) * PP + p];

    float py = offy + (float)(y - 1 + k / KHW);
    float px = offx + (float)(x - 1 + k % KHW);

    float y0f = floorf(py), x0f = floorf(px);
    float ly = py - y0f, lx = px - x0f;
    int y0 = (int)y0f, x0 = (int)x0f;
    int y1 = y0 + 1, x1 = x0 + 1;

    bool vy0 = (y0 >= 0) & (y0 < HH);
    bool vy1 = (y1 >= 0) & (y1 < HH);
    bool vx0 = (x0 >= 0) & (x0 < WW);
    bool vx1 = (x1 >= 0) & (x1 < WW);

    int cy0 = min(max(y0, 0), HH - 1), cy1 = min(max(y1, 0), HH - 1);
    int cx0 = min(max(x0, 0), WW - 1), cx1 = min(max(x1, 0), WW - 1);
    int o00 = cy0 * WW + cx0, o01 = cy0 * WW + cx1;
    int o10 = cy1 * WW + cx0, o11 = cy1 * WW + cx1;

    float w00 = (1.f - ly) * (1.f - lx) * ((vy0 & vx0) ? 1.f : 0.f) * mval;
    float w01 = (1.f - ly) * lx         * ((vy0 & vx1) ? 1.f : 0.f) * mval;
    float w10 = ly * (1.f - lx)         * ((vy1 & vx0) ? 1.f : 0.f) * mval;
    float w11 = ly * lx                 * ((vy1 & vx1) ? 1.f : 0.f) * mval;

    const float* base = g_inpt + (size_t)b * PP * CIN;
    const float4* r00 = reinterpret_cast<const float4*>(base + (size_t)o00 * CIN);
    const float4* r01 = reinterpret_cast<const float4*>(base + (size_t)o01 * CIN);
    const float4* r10 = reinterpret_cast<const float4*>(base + (size_t)o10 * CIN);
    const float4* r11 = reinterpret_cast<const float4*>(base + (size_t)o11 * CIN);

    uint32_t* outp = g_colsp + ((size_t)b * WPAIR + (size_t)k * 64) * PP + p;

    #pragma unroll 4
    for (int c4 = 0; c4 < 32; c4++) {
        float4 a = __ldg(r00 + c4);
        float4 bq = __ldg(r01 + c4);
        float4 c = __ldg(r10 + c4);
        float4 d = __ldg(r11 + c4);
        float v0 = w00 * a.x + w01 * bq.x + w10 * c.x + w11 * d.x;
        float v1 = w00 * a.y + w01 * bq.y + w10 * c.y + w11 * d.y;
        float v2 = w00 * a.z + w01 * bq.z + w10 * c.z + w11 * d.z;
        float v3 = w00 * a.w + w01 * bq.w + w10 * c.w + w11 * d.w;
        __half2 h0 = __halves2half2(__float2half_rn(v0), __float2half_rn(v1));
        __half2 h1 = __halves2half2(__float2half_rn(v2), __float2half_rn(v3));
        outp[(size_t)(2 * c4) * PP]     = *reinterpret_cast<uint32_t*>(&h0);
        outp[(size_t)(2 * c4 + 1) * PP] = *reinterpret_cast<uint32_t*>(&h1);
    }
}

// ---------------------------------------------------------------------------
// FP16 tensor-core GEMM (mma.m16n8k16, fp32 acc), cp.async 3-stage pipeline.
// Block tile 128(co) x 128(p) x 32(m'), 256 threads, warp tile 64x32.
// ---------------------------------------------------------------------------

#define BK 32
#define AST 20
#define BST 136
#define AW (128 * AST)
#define BW (16 * BST)
#define NSTG 3
#define SMEM_BYTES ((NSTG * (AW + BW)) * 4)   // 56832

__device__ __forceinline__ void cp16(uint32_t dst, const void* src) {
    asm volatile("cp.async.cg.shared.global [%0], [%1], 16;\n"
                 :: "r"(dst), "l"(src));
}

__global__ __launch_bounds__(256, 2) void gemm_f16_kernel(
    const float* __restrict__ bias,
    float* __restrict__ out)
{
    extern __shared__ uint32_t smem[];
    uint32_t* As0 = smem;
    uint32_t* Bs0 = smem + NSTG * AW;

    const int b  = blockIdx.z;
    const int n0 = blockIdx.x * 128;
    const uint32_t* Bsrc = g_colsp + (size_t)b * WPAIR * PP;

    const int tid  = threadIdx.x;
    const int wid  = tid >> 5;
    const int lane = tid & 31;
    const int wm = wid & 1;
    const int wn = wid >> 1;
    const int m_base = wm * 64;
    const int n_base = wn * 32;
    const int qr = lane >> 2;
    const int qc = lane & 3;

    const int a_co = tid >> 1;
    const int a_ch = (tid & 1) * 2;
    const int b_w  = tid >> 4;
    const int b_ch = (tid & 15) * 2;

    uint32_t smem_u32 = (uint32_t)__cvta_generic_to_shared(smem);
    const uint32_t a_smem = smem_u32;
    const uint32_t b_smem = smem_u32 + NSTG * AW * 4;

    float acc[4][4][4];
    #pragma unroll
    for (int mi = 0; mi < 4; mi++)
        #pragma unroll
        for (int ni = 0; ni < 4; ni++)
            #pragma unroll
            for (int c = 0; c < 4; c++) acc[mi][ni][c] = 0.f;

    auto issue = [&](int s, int i) {
        const uint32_t* asrc = g_wtp + ((size_t)i * 128 + a_co) * 16;
        uint32_t ad = a_smem + (uint32_t)(s * AW + a_co * AST) * 4;
        cp16(ad + (a_ch    ) * 16, asrc + (a_ch    ) * 4);
        cp16(ad + (a_ch + 1) * 16, asrc + (a_ch + 1) * 4);
        const uint32_t* bsrc = Bsrc + (size_t)(i * 16 + b_w) * PP + n0;
        uint32_t bd = b_smem + (uint32_t)(s * BW + b_w * BST) * 4;
        cp16(bd + (b_ch    ) * 16, bsrc + (b_ch    ) * 4);
        cp16(bd + (b_ch + 1) * 16, bsrc + (b_ch + 1) * 4);
    };

    issue(0, 0);
    asm volatile("cp.async.commit_group;\n");
    issue(1, 1);
    asm volatile("cp.async.commit_group;\n");

    for (int i = 0; i < NKT; i++) {
        if (i + 2 < NKT) issue((i + 2) % NSTG, i + 2);
        asm volatile("cp.async.commit_group;\n");
        asm volatile("cp.async.wait_group 2;\n");
        __syncthreads();

        const uint32_t* As_ = As0 + (size_t)(i % NSTG) * AW;
        const uint32_t* Bs_ = Bs0 + (size_t)(i % NSTG) * BW;

        #pragma unroll
        for (int ks = 0; ks < 2; ks++) {
            const int wb = ks * 8;
            uint32_t afr[4][4];
            uint32_t bfr[4][2];
            #pragma unroll
            for (int mi = 0; mi < 4; mi++) {
                int r = m_base + mi * 16 + qr;
                afr[mi][0] = As_[(r    ) * AST + wb + qc];
                afr[mi][1] = As_[(r + 8) * AST + wb + qc];
                afr[mi][2] = As_[(r    ) * AST + wb + qc + 4];
                afr[mi][3] = As_[(r + 8) * AST + wb + qc + 4];
            }
            #pragma unroll
            for (int ni = 0; ni < 4; ni++) {
                int n = n_base + ni * 8 + qr;
                bfr[ni][0] = Bs_[(wb + qc    ) * BST + n];
                bfr[ni][1] = Bs_[(wb + qc + 4) * BST + n];
            }
            #pragma unroll
            for (int mi = 0; mi < 4; mi++)
                #pragma unroll
                for (int ni = 0; ni < 4; ni++) {
                    asm volatile(
                        "mma.sync.aligned.m16n8k16.row.col.f32.f16.f16.f32 "
                        "{%0,%1,%2,%3}, {%4,%5,%6,%7}, {%8,%9}, {%0,%1,%2,%3};\n"
                        : "+f"(acc[mi][ni][0]), "+f"(acc[mi][ni][1]),
                          "+f"(acc[mi][ni][2]), "+f"(acc[mi][ni][3])
                        : "r"(afr[mi][0]), "r"(afr[mi][1]),
                          "r"(afr[mi][2]), "r"(afr[mi][3]),
                          "r"(bfr[ni][0]), "r"(bfr[ni][1]));
                }
        }
        __syncthreads();
    }

    float* outb = out + (size_t)b * COUT * PP;
    const int cr = lane >> 2;
    const int cc = (lane & 3) * 2;
    #pragma unroll
    for (int mi = 0; mi < 4; mi++) {
        int row = m_base + mi * 16 + cr;
        float bv0 = bias[row];
        float bv1 = bias[row + 8];
        #pragma unroll
        for (int ni = 0; ni < 4; ni++) {
            int col = n0 + n_base + ni * 8 + cc;
            float2 v0 = make_float2(acc[mi][ni][0] + bv0, acc[mi][ni][1] + bv0);
            float2 v1 = make_float2(acc[mi][ni][2] + bv1, acc[mi][ni][3] + bv1);
            *reinterpret_cast<float2*>(outb + (size_t)row * PP + col)       = v0;
            *reinterpret_cast<float2*>(outb + (size_t)(row + 8) * PP + col) = v1;
        }
    }
}

extern "C" void kernel_launch(void* const* d_in, const int* in_sizes, int n_in,
                              void* d_out, int out_size)
{
    const float* input  = (const float*)d_in[0];
    const float* offset = (const float*)d_in[1];
    const float* mask   = (const float*)d_in[2];
    const float* weight = (const float*)d_in[3];
    const float* bias   = (const float*)d_in[4];
    float* out = (float*)d_out;

    dim3 tg(PP / 32, CIN / 32, BB);           // (128, 4, 8)
    transpose_kernel<<<tg, 256>>>(input);
    wprep_kernel<<<(NKT * COUT * 16 + 255) / 256, 256>>>(weight);

    int total = BB * KK * PP;
    im2col_kernel<<<(total + 255) / 256, 256>>>(offset, mask);

    cudaFuncSetAttribute(gemm_f16_kernel,
                         cudaFuncAttributeMaxDynamicSharedMemorySize, SMEM_BYTES);
    dim3 grid(PP / 128, 1, BB);
    gemm_f16_kernel<<<grid, 256, SMEM_BYTES>>>(bias, out);
}

// round 17
// speedup vs baseline: 1.3593x; 1.3593x over previous
#include <cuda_runtime.h>
#include <cuda_fp16.h>
#include <math.h>
#include <stdint.h>

#define BB 8
#define CIN 128
#define COUT 128
#define HH 64
#define WW 64
#define KHW 3
#define KK 9
#define PP 4096            // Ho*Wo
#define MK 1152            // Cin*K  (reduction dim, reordered as m' = k*128 + c)
#define WPAIR 576          // MK/2
#define NKT 36             // MK/32 k-tiles

// Channel-last input: g_inpt[b][hw][c]  (16.8 MB)
__device__ float g_inpt[(size_t)BB * PP * CIN];
// Packed cols, p-major: g_colsp2[b*PP + p][w], w = k*64 + c/2.  75.5 MB
__device__ uint32_t g_colsp2[(size_t)BB * PP * WPAIR];
// Pre-tiled weights: [ktile][co][16 words], word j = half2(m'=kt*32+2j, +1)
__device__ uint32_t g_wtp[(size_t)NKT * COUT * 16];

// ---------------------------------------------------------------------------
// Input transpose: [b][c][hw] -> [b][hw][c], 32x32 smem tiles.
// ---------------------------------------------------------------------------
__global__ __launch_bounds__(256) void transpose_kernel(const float* __restrict__ input)
{
    __shared__ float tile[32][33];
    int b   = blockIdx.z;
    int hw0 = blockIdx.x * 32;
    int c0  = blockIdx.y * 32;
    int tx = threadIdx.x & 31;
    int ty = threadIdx.x >> 5;      // 0..7
    #pragma unroll
    for (int j = 0; j < 4; j++) {
        int c = c0 + ty + 8 * j;
        tile[ty + 8 * j][tx] = input[((size_t)b * CIN + c) * PP + hw0 + tx];
    }
    __syncthreads();
    #pragma unroll
    for (int j = 0; j < 4; j++) {
        int hw = hw0 + ty + 8 * j;
        g_inpt[((size_t)b * PP + hw) * CIN + c0 + tx] = tile[tx][ty + 8 * j];
    }
}

// ---------------------------------------------------------------------------
// Weight prep (unchanged ordering: m' = k*128 + c).
// ---------------------------------------------------------------------------
__global__ __launch_bounds__(256) void wprep_kernel(const float* __restrict__ Wt)
{
    int idx = blockIdx.x * blockDim.x + threadIdx.x;
    if (idx >= NKT * COUT * 16) return;
    int kt = idx >> 11;
    int co = (idx >> 4) & 127;
    int j  = idx & 15;
    int m0 = kt * 32 + 2 * j;
    int k  = m0 >> 7;
    int c  = m0 & 127;
    float w0 = Wt[(size_t)co * MK + c * KK + k];
    float w1 = Wt[(size_t)co * MK + (c + 1) * KK + k];
    __half2 h = __halves2half2(__float2half_rn(w0), __float2half_rn(w1));
    g_wtp[idx] = *reinterpret_cast<uint32_t*>(&h);
}

// ---------------------------------------------------------------------------
// Deformable im2col, warp-per-sample: one (b,k,p) per warp (2 per warp,
// interleaved). Lanes spread over channels: corner load = LDG.128 of 4
// contiguous channels -> fully coalesced 512B per warp instruction.
// Store: 64 contiguous words (STG.64/lane) into p-major cols.
// ---------------------------------------------------------------------------
__global__ __launch_bounds__(256) void im2col_kernel(
    const float* __restrict__ offset,
    const float* __restrict__ mask)
{
    const int gw   = (blockIdx.x * blockDim.x + threadIdx.x) >> 5;  // global warp
    const int lane = threadIdx.x & 31;

    const int NT = BB * KK * PP;
    int t0 = gw * 2;
    if (t0 >= NT) return;

    float4 v[2][4];
    float wgt[2][4];
    int pp[2], bb_[2], kk_[2];

    #pragma unroll
    for (int s = 0; s < 2; s++) {
        int t = t0 + s;
        int p  = t & (PP - 1);
        int kb = t >> 12;
        int k  = kb % KK;
        int b  = kb / KK;
        pp[s] = p; bb_[s] = b; kk_[s] = k;

        int y = p >> 6;
        int x = p & 63;

        float offy = __ldg(offset + ((size_t)b * 2 * KK + 2 * k) * PP + p);
        float offx = __ldg(offset + ((size_t)b * 2 * KK + 2 * k + 1) * PP + p);
        float mval = __ldg(mask + ((size_t)b * KK + k) * PP + p);

        float py = offy + (float)(y - 1 + k / KHW);
        float px = offx + (float)(x - 1 + k % KHW);

        float y0f = floorf(py), x0f = floorf(px);
        float ly = py - y0f, lx = px - x0f;
        int y0 = (int)y0f, x0 = (int)x0f;
        int y1 = y0 + 1, x1 = x0 + 1;

        bool vy0 = (y0 >= 0) & (y0 < HH);
        bool vy1 = (y1 >= 0) & (y1 < HH);
        bool vx0 = (x0 >= 0) & (x0 < WW);
        bool vx1 = (x1 >= 0) & (x1 < WW);

        int cy0 = min(max(y0, 0), HH - 1), cy1 = min(max(y1, 0), HH - 1);
        int cx0 = min(max(x0, 0), WW - 1), cx1 = min(max(x1, 0), WW - 1);
        int o00 = cy0 * WW + cx0, o01 = cy0 * WW + cx1;
        int o10 = cy1 * WW + cx0, o11 = cy1 * WW + cx1;

        wgt[s][0] = (1.f - ly) * (1.f - lx) * ((vy0 & vx0) ? 1.f : 0.f) * mval;
        wgt[s][1] = (1.f - ly) * lx         * ((vy0 & vx1) ? 1.f : 0.f) * mval;
        wgt[s][2] = ly * (1.f - lx)         * ((vy1 & vx0) ? 1.f : 0.f) * mval;
        wgt[s][3] = ly * lx                 * ((vy1 & vx1) ? 1.f : 0.f) * mval;

        const float* base = g_inpt + (size_t)b * PP * CIN + (size_t)lane * 4;
        v[s][0] = __ldg(reinterpret_cast<const float4*>(base + (size_t)o00 * CIN));
        v[s][1] = __ldg(reinterpret_cast<const float4*>(base + (size_t)o01 * CIN));
        v[s][2] = __ldg(reinterpret_cast<const float4*>(base + (size_t)o10 * CIN));
        v[s][3] = __ldg(reinterpret_cast<const float4*>(base + (size_t)o11 * CIN));
    }

    #pragma unroll
    for (int s = 0; s < 2; s++) {
        if (t0 + s >= NT) break;
        float r0 = wgt[s][0] * v[s][0].x + wgt[s][1] * v[s][1].x
                 + wgt[s][2] * v[s][2].x + wgt[s][3] * v[s][3].x;
        float r1 = wgt[s][0] * v[s][0].y + wgt[s][1] * v[s][1].y
                 + wgt[s][2] * v[s][2].y + wgt[s][3] * v[s][3].y;
        float r2 = wgt[s][0] * v[s][0].z + wgt[s][1] * v[s][1].z
                 + wgt[s][2] * v[s][2].z + wgt[s][3] * v[s][3].z;
        float r3 = wgt[s][0] * v[s][0].w + wgt[s][1] * v[s][1].w
                 + wgt[s][2] * v[s][2].w + wgt[s][3] * v[s][3].w;
        __half2 h0 = __halves2half2(__float2half_rn(r0), __float2half_rn(r1));
        __half2 h1 = __halves2half2(__float2half_rn(r2), __float2half_rn(r3));
        uint2 pkt = make_uint2(*reinterpret_cast<uint32_t*>(&h0),
                               *reinterpret_cast<uint32_t*>(&h1));
        uint32_t* dst = g_colsp2 + ((size_t)bb_[s] * PP + pp[s]) * WPAIR
                      + (size_t)kk_[s] * 64 + lane * 2;
        *reinterpret_cast<uint2*>(dst) = pkt;
    }
}

// ---------------------------------------------------------------------------
// FP16 tensor-core GEMM (mma.m16n8k16, fp32 acc), cp.async 3-stage pipeline.
// Block tile 128(co) x 128(p) x 32(m'), 256 threads, warp tile 64x32.
// A smem [co][16w + pad], B smem [p][16w + pad] (symmetric addressing).
// ---------------------------------------------------------------------------

#define AST 20                  // row stride (words) for both A and B smem
#define AW (128 * AST)          // 2560 words / stage
#define NSTG 3
#define SMEM_BYTES ((NSTG * 2 * AW) * 4)   // 61440

__device__ __forceinline__ void cp16(uint32_t dst, const void* src) {
    asm volatile("cp.async.cg.shared.global [%0], [%1], 16;\n"
                 :: "r"(dst), "l"(src));
}

__global__ __launch_bounds__(256, 2) void gemm_f16_kernel(
    const float* __restrict__ bias,
    float* __restrict__ out)
{
    extern __shared__ uint32_t smem[];
    uint32_t* As0 = smem;                   // [NSTG][AW]
    uint32_t* Bs0 = smem + NSTG * AW;       // [NSTG][AW]

    const int b  = blockIdx.z;
    const int n0 = blockIdx.x * 128;
    const uint32_t* Bsrc = g_colsp2 + ((size_t)b * PP + n0) * WPAIR;

    const int tid  = threadIdx.x;
    const int wid  = tid >> 5;
    const int lane = tid & 31;
    const int wm = wid & 1;
    const int wn = wid >> 1;
    const int m_base = wm * 64;
    const int n_base = wn * 32;
    const int qr = lane >> 2;
    const int qc = lane & 3;

    // cp.async mapping (same for A and B): 512 chunks = 128 rows x 4
    const int l_row = tid >> 1;
    const int l_ch  = (tid & 1) * 2;

    uint32_t smem_u32 = (uint32_t)__cvta_generic_to_shared(smem);
    const uint32_t a_smem = smem_u32;
    const uint32_t b_smem = smem_u32 + NSTG * AW * 4;

    float acc[4][4][4];
    #pragma unroll
    for (int mi = 0; mi < 4; mi++)
        #pragma unroll
        for (int ni = 0; ni < 4; ni++)
            #pragma unroll
            for (int c = 0; c < 4; c++) acc[mi][ni][c] = 0.f;

    auto issue = [&](int s, int i) {
        const uint32_t* asrc = g_wtp + ((size_t)i * 128 + l_row) * 16;
        uint32_t ad = a_smem + (uint32_t)(s * AW + l_row * AST) * 4;
        cp16(ad + (l_ch    ) * 16, asrc + (l_ch    ) * 4);
        cp16(ad + (l_ch + 1) * 16, asrc + (l_ch + 1) * 4);
        const uint32_t* bsrc = Bsrc + (size_t)l_row * WPAIR + i * 16;
        uint32_t bd = b_smem + (uint32_t)(s * AW + l_row * AST) * 4;
        cp16(bd + (l_ch    ) * 16, bsrc + (l_ch    ) * 4);
        cp16(bd + (l_ch + 1) * 16, bsrc + (l_ch + 1) * 4);
    };

    issue(0, 0);
    asm volatile("cp.async.commit_group;\n");
    issue(1, 1);
    asm volatile("cp.async.commit_group;\n");

    for (int i = 0; i < NKT; i++) {
        if (i + 2 < NKT) issue((i + 2) % NSTG, i + 2);
        asm volatile("cp.async.commit_group;\n");
        asm volatile("cp.async.wait_group 2;\n");
        __syncthreads();

        const uint32_t* As_ = As0 + (size_t)(i % NSTG) * AW;
        const uint32_t* Bs_ = Bs0 + (size_t)(i % NSTG) * AW;

        #pragma unroll
        for (int ks = 0; ks < 2; ks++) {
            const int wb = ks * 8;
            uint32_t afr[4][4];
            uint32_t bfr[4][2];
            #pragma unroll
            for (int mi = 0; mi < 4; mi++) {
                int r = m_base + mi * 16 + qr;
                afr[mi][0] = As_[(r    ) * AST + wb + qc];
                afr[mi][1] = As_[(r + 8) * AST + wb + qc];
                afr[mi][2] = As_[(r    ) * AST + wb + qc + 4];
                afr[mi][3] = As_[(r + 8) * AST + wb + qc + 4];
            }
            #pragma unroll
            for (int ni = 0; ni < 4; ni++) {
                int n = n_base + ni * 8 + qr;
                bfr[ni][0] = Bs_[n * AST + wb + qc];
                bfr[ni][1] = Bs_[n * AST + wb + qc + 4];
            }
            #pragma unroll
            for (int mi = 0; mi < 4; mi++)
                #pragma unroll
                for (int ni = 0; ni < 4; ni++) {
                    asm volatile(
                        "mma.sync.aligned.m16n8k16.row.col.f32.f16.f16.f32 "
                        "{%0,%1,%2,%3}, {%4,%5,%6,%7}, {%8,%9}, {%0,%1,%2,%3};\n"
                        : "+f"(acc[mi][ni][0]), "+f"(acc[mi][ni][1]),
                          "+f"(acc[mi][ni][2]), "+f"(acc[mi][ni][3])
                        : "r"(afr[mi][0]), "r"(afr[mi][1]),
                          "r"(afr[mi][2]), "r"(afr[mi][3]),
                          "r"(bfr[ni][0]), "r"(bfr[ni][1]));
                }
        }
        __syncthreads();
    }

    float* outb = out + (size_t)b * COUT * PP;
    const int cr = lane >> 2;
    const int cc = (lane & 3) * 2;
    #pragma unroll
    for (int mi = 0; mi < 4; mi++) {
        int row = m_base + mi * 16 + cr;
        float bv0 = bias[row];
        float bv1 = bias[row + 8];
        #pragma unroll
        for (int ni = 0; ni < 4; ni++) {
            int col = n0 + n_base + ni * 8 + cc;
            float2 v0 = make_float2(acc[mi][ni][0] + bv0, acc[mi][ni][1] + bv0);
            float2 v1 = make_float2(acc[mi][ni][2] + bv1, acc[mi][ni][3] + bv1);
            *reinterpret_cast<float2*>(outb + (size_t)row * PP + col)       = v0;
            *reinterpret_cast<float2*>(outb + (size_t)(row + 8) * PP + col) = v1;
        }
    }
}

extern "C" void kernel_launch(void* const* d_in, const int* in_sizes, int n_in,
                              void* d_out, int out_size)
{
    const float* input  = (const float*)d_in[0];
    const float* offset = (const float*)d_in[1];
    const float* mask   = (const float*)d_in[2];
    const float* weight = (const float*)d_in[3];
    const float* bias   = (const float*)d_in[4];
    float* out = (float*)d_out;

    dim3 tg(PP / 32, CIN / 32, BB);           // (128, 4, 8)
    transpose_kernel<<<tg, 256>>>(input);
    wprep_kernel<<<(NKT * COUT * 16 + 255) / 256, 256>>>(weight);

    // one (b,k,p) per warp, 2 per warp: tasks/2 warps, 8 warps/block
    int nblk = (BB * KK * PP) / 2 / 8;        // 18432
    im2col_kernel<<<nblk, 256>>>(offset, mask);

    cudaFuncSetAttribute(gemm_f16_kernel,
                         cudaFuncAttributeMaxDynamicSharedMemorySize, SMEM_BYTES);
    dim3 grid(PP / 128, 1, BB);
    gemm_f16_kernel<<<grid, 256, SMEM_BYTES>>>(bias, out);
}